// round 14
// baseline (speedup 1.0000x reference)
#include <cuda_runtime.h>
#include <math.h>

#define NBLK 64
#define NTH  256
#define INV_SQRT_D 0.08838834764831845f

__device__ float    g_slots[2][8][64][128];
__device__ float    g_qk[8][128];
__device__ float    g_halt2[2][8];
__device__ float    g_wqk[128][128];
__device__ float    g_M[128][768];
__device__ float    g_woutT[768][128];
__device__ unsigned g_arr[64];          // per-block arrival flags (memset each launch)

__device__ __forceinline__ float wsum(float v) {
    #pragma unroll
    for (int o = 16; o; o >>= 1) v += __shfl_xor_sync(0xffffffffu, v, o);
    return v;
}

// all-poll-all barrier: block publishes its round, warp 0 polls all 64 flags.
__device__ __forceinline__ void gbar(unsigned& round, int blk) {
    round++;
    __syncthreads();
    if (threadIdx.x < 32) {
        if (threadIdx.x == 0) {
            __threadfence();
            *(volatile unsigned*)&g_arr[blk] = round;
        }
        unsigned a0, a1;
        do {
            a0 = *(volatile unsigned*)&g_arr[threadIdx.x];
            a1 = *(volatile unsigned*)&g_arr[threadIdx.x + 32];
        } while (!__all_sync(0xffffffffu, a0 >= round && a1 >= round));
        __threadfence();
    }
    __syncthreads();
}

__global__ void __launch_bounds__(NTH, 1)
ssb_kernel(const float* __restrict__ x,      const float* __restrict__ slot_mem,
           const float* __restrict__ ln_w,   const float* __restrict__ ln_b,
           const float* __restrict__ w_in,   const float* __restrict__ w_q,
           const float* __restrict__ w_k,    const float* __restrict__ w_v,
           const float* __restrict__ w_gate, const float* __restrict__ b_gate,
           const float* __restrict__ hw1,    const float* __restrict__ hb1,
           const float* __restrict__ hw2,    const float* __restrict__ hb2,
           const float* __restrict__ w_out,  const float* __restrict__ dn_wk,
           const float* __restrict__ dn_wv,  const float* __restrict__ dn_wb,
           const float* __restrict__ dn_bb,  const float* __restrict__ dn_lam,
           const float* __restrict__ dn_wo,  float* __restrict__ out)
{
    extern __shared__ float dyn[];
    float* s_wo   = dyn;                                  // dn_wo [d][j]  64KB
    float* s_wv   = dyn + 16384;                          // w_v           64KB
    float (*s_bank)[128] = (float(*)[128])(dyn + 32768);  // 64 slot rows  32KB
    float* s_hw1  = dyn + 40960;                          // hw1 [e][j]    32KB

    __shared__ __align__(16) float s_ls[8][132];
    __shared__ __align__(16) float s_xn[768];
    __shared__ __align__(16) float s_qk[128];
    __shared__ __align__(16) float s_ro[128], s_k[128], s_bv[128], s_acc[128];
    __shared__ __align__(16) float s_u[4][128];
    __shared__ __align__(16) float s_p2[2][128], s_pc[2][128];
    __shared__ __align__(16) float s_kp[8][128], s_vp[8][128];
    __shared__ __align__(16) float s_wg[8][128];
    __shared__ __align__(16) float s_wbT[4][128];
    __shared__ float s_hp[4][64];
    __shared__ float s_att[64], s_h1[64];
    __shared__ float s_lam[128], s_hb1[64], s_hw2[64];
    __shared__ float s_beta[4], s_gate[8], s_kh[8][4], s_bg[8], s_bb[4];
    __shared__ float s_red[9];
    __shared__ float s_sc[4];

    const int tid = threadIdx.x, lane = tid & 31, wid = tid >> 5;
    const int blk = blockIdx.x, b = blk >> 3, sub = blk & 7, n0 = sub * 8;
    unsigned round = 0;
    int p = 0;
    const float hb2v = hb2[0];

    // ---- one-time precompute: wqk, M = w_in@(w_q@w_k^T), woutT ----
    for (int r = 0; r < 2; r++) {
        int d = blk * 2 + r;
        if (tid < 128) s_xn[tid] = w_q[d * 128 + tid];
        __syncthreads();
        for (int e = wid; e < 128; e += 8) {
            const float* wkr = w_k + e * 128;
            float a = s_xn[lane] * wkr[lane] + s_xn[lane + 32] * wkr[lane + 32]
                    + s_xn[lane + 64] * wkr[lane + 64] + s_xn[lane + 96] * wkr[lane + 96];
            a = wsum(a);
            if (lane == 0) g_wqk[d][e] = a;
        }
        __syncthreads();
    }
    for (int i = tid; i < 12 * 128; i += NTH) {
        int r = i >> 7, d = i & 127;
        g_woutT[blk * 12 + r][d] = w_out[d * 768 + blk * 12 + r];
    }
    gbar(round, blk);
    for (int r = 0; r < 2; r++) {
        int e = blk * 2 + r;
        if (tid < 128) s_xn[tid] = __ldcg(&g_wqk[tid][e]);
        __syncthreads();
        for (int i = tid; i < 768; i += NTH) {
            const float* wir = w_in + i * 128;
            float a = 0.f;
            #pragma unroll 8
            for (int d = 0; d < 128; d++) a += wir[d] * s_xn[d];
            g_M[e][i] = a;
        }
        __syncthreads();
    }

    // ---- smem caches ----
    for (int i = tid * 4; i < 16384; i += NTH * 4) {
        *(float4*)(s_wo + i) = *(const float4*)(dn_wo + i);
        *(float4*)(s_wv + i) = *(const float4*)(w_v + i);
    }
    for (int i = tid * 4; i < 8192; i += NTH * 4)
        *(float4*)(s_hw1 + i) = *(const float4*)(hw1 + i);
    for (int i = tid; i < 1024; i += NTH) {
        int n = i >> 7, d = i & 127;
        s_wg[n][d] = w_gate[d * 64 + (n0 + n)];
    }
    for (int i = tid; i < 512; i += NTH) {
        int h = i >> 7, d = i & 127;
        s_wbT[h][d] = dn_wb[d * 4 + h];
    }
    if (tid < 128) s_lam[tid] = dn_lam[tid];
    if (tid < 64) { s_hb1[tid] = hb1[tid]; s_hw2[tid] = hw2[tid]; }
    if (tid < 8) s_bg[tid] = b_gate[n0 + tid];
    if (tid < 4) s_bb[tid] = dn_bb[tid];
    for (int i = tid; i < 8192; i += NTH) {
        int n = i >> 7, d = i & 127;
        s_bank[n][d] = slot_mem[i];
    }
    for (int i = tid; i < 1024; i += NTH) {
        int n = i >> 7, d = i & 127;
        g_slots[0][b][n0 + n][d] = s_bank[n0 + n][d];
    }
    gbar(round, blk);

    for (int t = 0; t < 128; t++) {
        const float* xr = x + (b * 128 + t) * 768;
        // ---- layernorm ----
        float ps = 0.f;
        for (int i = tid; i < 768; i += NTH) { float v = xr[i]; s_xn[i] = v; ps += v; }
        ps = wsum(ps); if (lane == 0) s_red[wid] = ps;
        __syncthreads();
        if (tid == 0) { float s = 0; for (int i = 0; i < 8; i++) s += s_red[i]; s_sc[3] = s * (1.f / 768.f); }
        __syncthreads();
        float mu = s_sc[3], pv = 0.f;
        for (int i = tid; i < 768; i += NTH) { float d2 = s_xn[i] - mu; pv += d2 * d2; }
        pv = wsum(pv); if (lane == 0) s_red[wid] = pv;
        __syncthreads();
        if (tid == 0) { float s = 0; for (int i = 0; i < 8; i++) s += s_red[i]; s_sc[3] = rsqrtf(s * (1.f / 768.f) + 1e-5f); }
        __syncthreads();
        float rstd = s_sc[3];
        for (int i = tid; i < 768; i += NTH) s_xn[i] = (s_xn[i] - mu) * rstd * ln_w[i] + ln_b[i];
        __syncthreads();
        // ---- qk slice (16 entries per block) ----
        {
            int e = sub * 16 + wid * 2;
            #pragma unroll
            for (int sel = 0; sel < 2; sel++) {
                const float* Mr = &g_M[e + sel][0];
                float a = 0.f;
                #pragma unroll
                for (int i = lane; i < 768; i += 32) a += s_xn[i] * Mr[i];
                a = wsum(a);
                if (lane == 0) g_qk[b][e + sel] = a;
            }
        }
        float accl = 0.f, reml = 1.f;
        gbar(round, blk);
        if (tid < 128) s_qk[tid] = __ldcg(&g_qk[b][tid]);
        __syncthreads();

        // ================= tick loop =================
        for (int tt = 0; tt < 8; tt++) {
            // A: import sibling rows + s_ls
            {
                const float* gsl = &g_slots[p][b][0][0];
                #pragma unroll
                for (int it = 0; it < 8; it++) {
                    int i = it * NTH + tid;
                    int row = i >> 5, c4 = i & 31;
                    if ((row >> 3) != sub)
                        *(float4*)&s_bank[row][c4 * 4] = __ldcg((const float4*)(gsl + row * 128) + c4);
                }
                for (int i = tid; i < 1024; i += NTH) {
                    int n = i >> 7, d = i & 127;
                    s_ls[n][d] = s_lam[d] * s_bank[n0 + n][d];
                }
            }
            __syncthreads();
            // B: scores
            {
                float4 q4 = *(const float4*)&s_qk[lane * 4];
                float sc[8];
                #pragma unroll
                for (int k2 = 0; k2 < 8; k2++) {
                    int n = wid + (k2 << 3);
                    float4 s4 = *(const float4*)&s_bank[n][lane * 4];
                    sc[k2] = q4.x * s4.x + q4.y * s4.y + q4.z * s4.z + q4.w * s4.w;
                }
                #pragma unroll
                for (int k2 = 0; k2 < 8; k2++) {
                    float a = wsum(sc[k2]);
                    if (lane == 0) s_att[wid + (k2 << 3)] = a * INV_SQRT_D;
                }
            }
            __syncthreads();
            // C: softmax in warp 0
            if (wid == 0) {
                float a0 = s_att[lane], a1 = s_att[lane + 32];
                float m = fmaxf(a0, a1);
                #pragma unroll
                for (int o = 16; o; o >>= 1) m = fmaxf(m, __shfl_xor_sync(0xffffffffu, m, o));
                float e0 = expf(a0 - m), e1 = expf(a1 - m);
                float s = wsum(e0 + e1);
                float inv = 1.f / s;
                s_att[lane] = e0 * inv; s_att[lane + 32] = e1 * inv;
            }
            __syncthreads();
            // D: sbar partials
            {
                int d = tid & 127, ph = tid >> 7;
                float a = 0.f;
                #pragma unroll 8
                for (int n2 = 0; n2 < 32; n2++) a += s_att[ph * 32 + n2] * s_bank[ph * 32 + n2][d];
                s_p2[ph][d] = a;
            }
            __syncthreads();
            // E: ro = sbar @ w_v
            {
                int d = tid & 127, ph = tid >> 7;
                float a = 0.f;
                #pragma unroll 8
                for (int e = 0; e < 64; e++) {
                    float se = s_p2[0][ph * 64 + e] + s_p2[1][ph * 64 + e];
                    a += se * s_wv[(ph * 64 + e) * 128 + d];
                }
                s_pc[ph][d] = a;
            }
            __syncthreads();
            if (tid < 128) s_ro[tid] = s_pc[0][tid] + s_pc[1][tid];
            __syncthreads();
            // F: gate + beta + halt partials
            {
                float4 r4 = *(const float4*)&s_ro[lane * 4];
                float4 w4 = *(const float4*)&s_wg[wid][lane * 4];
                float a = r4.x * w4.x + r4.y * w4.y + r4.z * w4.z + r4.w * w4.w;
                a = wsum(a);
                if (lane == 0) s_gate[wid] = 1.f / (1.f + expf(-(a + s_bg[wid])));
            }
            if (wid < 4) {
                float a = s_ro[lane] * s_wbT[wid][lane] + s_ro[lane + 32] * s_wbT[wid][lane + 32]
                        + s_ro[lane + 64] * s_wbT[wid][lane + 64] + s_ro[lane + 96] * s_wbT[wid][lane + 96];
                a = wsum(a);
                if (lane == 0) s_beta[wid] = 2.f / (1.f + expf(-(a + s_bb[wid])));
            }
            {
                int j = tid & 63, p4 = tid >> 6;
                const float* h1p = s_hw1 + p4 * 32 * 64 + j;
                float a0 = 0.f, a1 = 0.f;
                #pragma unroll
                for (int e = 0; e < 32; e += 2) {
                    a0 += s_ro[p4 * 32 + e] * h1p[e * 64];
                    a1 += s_ro[p4 * 32 + e + 1] * h1p[(e + 1) * 64];
                }
                s_hp[p4][j] = a0 + a1;
            }
            __syncthreads();
            // G: halt finish + publish
            if (tid < 64)
                s_h1[tid] = fmaxf(s_hp[0][tid] + s_hp[1][tid] + s_hp[2][tid] + s_hp[3][tid] + s_hb1[tid], 0.f);
            __syncthreads();
            if (wid == 0) {
                float pv2 = s_h1[lane] * s_hw2[lane] + s_h1[lane + 32] * s_hw2[lane + 32];
                pv2 = wsum(pv2);
                if (lane == 0) {
                    float hl = 1.f / (1.f + expf(-(pv2 + hb2v)));
                    s_sc[1] = hl;
                    if (sub == 0) __stcg(&g_halt2[p][b], hl);
                }
            }
            __syncthreads();
            if (tid < 128) accl += reml * s_ro[tid];
            if (tt < 7) reml *= (1.f - s_sc[1]);
            // H: k & v fused float4 GEMVs from L2
            {
                int dq = lane, part = wid;
                float4 ka = make_float4(0, 0, 0, 0), va = ka;
                #pragma unroll
                for (int e = 0; e < 16; e++) {
                    int ee = part * 16 + e;
                    float r = s_ro[ee];
                    float4 wk4 = __ldcg((const float4*)(dn_wk + ee * 128) + dq);
                    float4 wv4 = __ldcg((const float4*)(dn_wv + ee * 128) + dq);
                    ka.x += r * wk4.x; ka.y += r * wk4.y; ka.z += r * wk4.z; ka.w += r * wk4.w;
                    va.x += r * wv4.x; va.y += r * wv4.y; va.z += r * wv4.z; va.w += r * wv4.w;
                }
                *(float4*)&s_kp[part][dq * 4] = ka;
                *(float4*)&s_vp[part][dq * 4] = va;
            }
            __syncthreads();
            if (tid < 128) {
                float kr = 0.f, vr = 0.f;
                #pragma unroll
                for (int pp = 0; pp < 8; pp++) { kr += s_kp[pp][tid]; vr += s_vp[pp][tid]; }
                float sq = wsum(kr * kr);
                s_k[tid] = kr / (sqrtf(sq) + 1e-6f);
                s_bv[tid] = s_beta[tid >> 5] * vr;
            }
            __syncthreads();
            // I: c partials + u + kh
            {
                int j = tid & 127, ph = tid >> 7;
                const float* wop = s_wo + ph * 64 * 128 + j;
                float a = 0.f;
                #pragma unroll 8
                for (int d2 = 0; d2 < 64; d2++) a += s_bv[ph * 64 + d2] * wop[d2 * 128];
                s_pc[ph][j] = a;
            }
            {
                int j = tid & 127, h0 = tid >> 7;
                #pragma unroll
                for (int q2 = 0; q2 < 2; q2++) {
                    int h = h0 + 2 * q2;
                    const float* wop = s_wo + h * 32 * 128 + j;
                    float a = 0.f;
                    #pragma unroll 8
                    for (int dh = 0; dh < 32; dh++) a += s_k[h * 32 + dh] * wop[dh * 128];
                    s_u[h][j] = s_beta[h] * a;
                }
            }
            {
                const float* srow = s_bank[n0 + wid];
                float t0 = s_k[lane] * srow[lane];
                float t1 = s_k[lane + 32] * srow[lane + 32];
                float t2 = s_k[lane + 64] * srow[lane + 64];
                float t3 = s_k[lane + 96] * srow[lane + 96];
                t0 = wsum(t0); t1 = wsum(t1); t2 = wsum(t2); t3 = wsum(t3);
                if (lane == 0) { s_kh[wid][0] = t0; s_kh[wid][1] = t1; s_kh[wid][2] = t2; s_kh[wid][3] = t3; }
            }
            __syncthreads();
            // J: update GEMM + blend + write
            {
                int n = lane >> 2, j0 = wid * 16 + (lane & 3) * 4;
                float4 c0 = *(const float4*)&s_pc[0][j0];
                float4 c1 = *(const float4*)&s_pc[1][j0];
                float4 r = make_float4(c0.x + c1.x, c0.y + c1.y, c0.z + c1.z, c0.w + c1.w);
                #pragma unroll 4
                for (int d2 = 0; d2 < 128; d2++) {
                    float lv = s_ls[n][d2];
                    float4 w4 = *(const float4*)(s_wo + d2 * 128 + j0);
                    r.x += lv * w4.x; r.y += lv * w4.y; r.z += lv * w4.z; r.w += lv * w4.w;
                }
                #pragma unroll
                for (int h = 0; h < 4; h++) {
                    float kv = s_kh[n][h];
                    const float* uu = s_u[h];
                    r.x -= kv * uu[j0]; r.y -= kv * uu[j0 + 1]; r.z -= kv * uu[j0 + 2]; r.w -= kv * uu[j0 + 3];
                }
                float g = s_gate[n];
                float4 sv = *(const float4*)&s_bank[n0 + n][j0];
                float4 nv;
                nv.x = (1.f - g) * sv.x + g * r.x;
                nv.y = (1.f - g) * sv.y + g * r.y;
                nv.z = (1.f - g) * sv.z + g * r.z;
                nv.w = (1.f - g) * sv.w + g * r.w;
                __stcg((float4*)&g_slots[1 - p][b][n0 + n][j0], nv);
                __syncwarp();
                *(float4*)&s_bank[n0 + n][j0] = nv;
            }
            int oldp = p;
            p ^= 1;
            if (tt < 7) {
                gbar(round, blk);       // syncs slot writes; tick-7 sync is covered by the qk barrier
                if (tt > 0) {
                    if (tid == 0) {
                        float s2 = 0;
                        #pragma unroll
                        for (int i = 0; i < 8; i++) s2 += __ldcg(&g_halt2[oldp][i]);
                        s_sc[2] = ((s2 * 0.125f) > 0.5f) ? 1.f : 0.f;
                    }
                    __syncthreads();
                    if (s_sc[2] != 0.f) break;
                }
            }
        } // ticks

        if (tid < 128) s_acc[tid] = accl;
        __syncthreads();
        // out_t = acc @ w_out (transposed rows, float4)
        if (tid < 96) {
            int jg = sub * 96 + tid;
            const float4* wp = (const float4*)&g_woutT[jg][0];
            float a = 0.f;
            #pragma unroll
            for (int i = 0; i < 32; i++) {
                float4 w4 = __ldcg(wp + i);
                float4 ac = *(const float4*)&s_acc[i * 4];
                a += w4.x * ac.x + w4.y * ac.y + w4.z * ac.z + w4.w * ac.w;
            }
            out[(b * 128 + t) * 768 + jg] = a;
        }
    } // steps

    // slots_final
    {
        float* so = out + 8 * 128 * 768;
        for (int i = tid; i < 1024; i += NTH) {
            int n = i >> 7, d = i & 127;
            so[(b * 64 + n0 + n) * 128 + d] = s_bank[n0 + n][d];
        }
    }
}

extern "C" void kernel_launch(void* const* d_in, const int* in_sizes, int n_in,
                              void* d_out, int out_size) {
    const float* x        = (const float*)d_in[0];
    const float* slot_mem = (const float*)d_in[1];
    const float* ln_w     = (const float*)d_in[2];
    const float* ln_b     = (const float*)d_in[3];
    const float* w_in     = (const float*)d_in[4];
    const float* w_q      = (const float*)d_in[5];
    const float* w_k      = (const float*)d_in[6];
    const float* w_v      = (const float*)d_in[7];
    const float* w_gate   = (const float*)d_in[8];
    const float* b_gate   = (const float*)d_in[9];
    const float* hw1      = (const float*)d_in[10];
    const float* hb1      = (const float*)d_in[11];
    const float* hw2      = (const float*)d_in[12];
    const float* hb2      = (const float*)d_in[13];
    const float* w_out    = (const float*)d_in[14];
    const float* dn_wk    = (const float*)d_in[15];
    const float* dn_wv    = (const float*)d_in[16];
    const float* dn_wb    = (const float*)d_in[17];
    const float* dn_bb    = (const float*)d_in[18];
    const float* dn_lam   = (const float*)d_in[19];
    const float* dn_wo    = (const float*)d_in[20];
    float* out = (float*)d_out;

    void* sa = nullptr;
    cudaGetSymbolAddress(&sa, g_arr);
    cudaMemsetAsync(sa, 0, 64 * sizeof(unsigned), 0);

    cudaFuncSetAttribute(ssb_kernel, cudaFuncAttributeMaxDynamicSharedMemorySize, 196608);
    ssb_kernel<<<NBLK, NTH, 196608>>>(x, slot_mem, ln_w, ln_b, w_in, w_q, w_k, w_v,
                                      w_gate, b_gate, hw1, hb1, hw2, hb2, w_out,
                                      dn_wk, dn_wv, dn_wb, dn_bb, dn_lam, dn_wo, out);
}

// round 15
// speedup vs baseline: 1.3466x; 1.3466x over previous
#include <cuda_runtime.h>
#include <math.h>

#define NBLK 64
#define NTH  256
#define INV_SQRT_D 0.08838834764831845f

__device__ float    g_slots[2][8][64][128];
__device__ float    g_qk[8][128];
__device__ float    g_wqk[128][128];
__device__ float    g_M[128][768];
__device__ float    g_woutT[768][128];
__device__ unsigned long long g_hmail[8][8];  // per-batch halt mailbox ring (memset each launch)
__device__ unsigned g_sync[2];                // startup barrier (memset each launch)

__device__ __forceinline__ float wsum(float v) {
    #pragma unroll
    for (int o = 16; o; o >>= 1) v += __shfl_xor_sync(0xffffffffu, v, o);
    return v;
}

// startup-only global barrier (atomic; used 2x)
__device__ __forceinline__ void gbar(unsigned& round) {
    __syncthreads();
    if (threadIdx.x == 0) {
        __threadfence();
        unsigned tk = atomicAdd(&g_sync[0], 1u);
        if (tk == NBLK - 1u) {
            g_sync[0] = 0u;
            __threadfence();
            *(volatile unsigned*)&g_sync[1] = round + 1u;
        } else {
            while (*(volatile unsigned*)&g_sync[1] < round + 1u) {}
            __threadfence();
        }
    }
    round++;
    __syncthreads();
}

// cluster-wide barrier (8 CTAs of one batch); orders stcg/ldcg via release/acquire
__device__ __forceinline__ void csync() {
    asm volatile("barrier.cluster.arrive.aligned;" ::: "memory");
    asm volatile("barrier.cluster.wait.aligned;"   ::: "memory");
}

__global__ void __launch_bounds__(NTH, 1) __cluster_dims__(8, 1, 1)
ssb_kernel(const float* __restrict__ x,      const float* __restrict__ slot_mem,
           const float* __restrict__ ln_w,   const float* __restrict__ ln_b,
           const float* __restrict__ w_in,   const float* __restrict__ w_q,
           const float* __restrict__ w_k,    const float* __restrict__ w_v,
           const float* __restrict__ w_gate, const float* __restrict__ b_gate,
           const float* __restrict__ hw1,    const float* __restrict__ hb1,
           const float* __restrict__ hw2,    const float* __restrict__ hb2,
           const float* __restrict__ w_out,  const float* __restrict__ dn_wk,
           const float* __restrict__ dn_wv,  const float* __restrict__ dn_wb,
           const float* __restrict__ dn_bb,  const float* __restrict__ dn_lam,
           const float* __restrict__ dn_wo,  float* __restrict__ out)
{
    extern __shared__ float dyn[];
    float* s_wo   = dyn;                                  // dn_wo [d][j]  64KB
    float* s_wv   = dyn + 16384;                          // w_v           64KB
    float (*s_bank)[128] = (float(*)[128])(dyn + 32768);  // 64 slot rows  32KB
    float* s_hw1  = dyn + 40960;                          // hw1 [e][j]    32KB

    __shared__ __align__(16) float s_ls[8][132];
    __shared__ __align__(16) float s_xn[768];
    __shared__ __align__(16) float s_qk[128];
    __shared__ __align__(16) float s_ro[128], s_k[128], s_bv[128], s_acc[128];
    __shared__ __align__(16) float s_u[4][128];
    __shared__ __align__(16) float s_p2[2][128], s_pc[2][128];
    __shared__ __align__(16) float s_kp[8][128], s_vp[8][128];
    __shared__ __align__(16) float s_wg[8][128];
    __shared__ __align__(16) float s_wbT[4][128];
    __shared__ float s_hp[4][64];
    __shared__ float s_att[64], s_h1[64];
    __shared__ float s_lam[128], s_hb1[64], s_hw2[64];
    __shared__ float s_beta[4], s_gate[8], s_kh[8][4], s_bg[8], s_bb[4];
    __shared__ float s_red[9];
    __shared__ float s_sc[4];

    const int tid = threadIdx.x, lane = tid & 31, wid = tid >> 5;
    const int blk = blockIdx.x, b = blk >> 3, sub = blk & 7, n0 = sub * 8;
    unsigned round = 0;
    unsigned gt = 0;                 // executed-tick counter (uniform across all blocks)
    int p = 0;
    const float hb2v = hb2[0];

    // ---- one-time precompute: wqk, M = w_in@(w_q@w_k^T), woutT ----
    for (int r = 0; r < 2; r++) {
        int d = blk * 2 + r;
        if (tid < 128) s_xn[tid] = w_q[d * 128 + tid];
        __syncthreads();
        for (int e = wid; e < 128; e += 8) {
            const float* wkr = w_k + e * 128;
            float a = s_xn[lane] * wkr[lane] + s_xn[lane + 32] * wkr[lane + 32]
                    + s_xn[lane + 64] * wkr[lane + 64] + s_xn[lane + 96] * wkr[lane + 96];
            a = wsum(a);
            if (lane == 0) g_wqk[d][e] = a;
        }
        __syncthreads();
    }
    for (int i = tid; i < 12 * 128; i += NTH) {
        int r = i >> 7, d = i & 127;
        g_woutT[blk * 12 + r][d] = w_out[d * 768 + blk * 12 + r];
    }
    gbar(round);
    for (int r = 0; r < 2; r++) {
        int e = blk * 2 + r;
        if (tid < 128) s_xn[tid] = __ldcg(&g_wqk[tid][e]);
        __syncthreads();
        for (int i = tid; i < 768; i += NTH) {
            const float* wir = w_in + i * 128;
            float a = 0.f;
            #pragma unroll 8
            for (int d = 0; d < 128; d++) a += wir[d] * s_xn[d];
            g_M[e][i] = a;
        }
        __syncthreads();
    }

    // ---- smem caches ----
    for (int i = tid * 4; i < 16384; i += NTH * 4) {
        *(float4*)(s_wo + i) = *(const float4*)(dn_wo + i);
        *(float4*)(s_wv + i) = *(const float4*)(w_v + i);
    }
    for (int i = tid * 4; i < 8192; i += NTH * 4)
        *(float4*)(s_hw1 + i) = *(const float4*)(hw1 + i);
    for (int i = tid; i < 1024; i += NTH) {
        int n = i >> 7, d = i & 127;
        s_wg[n][d] = w_gate[d * 64 + (n0 + n)];
    }
    for (int i = tid; i < 512; i += NTH) {
        int h = i >> 7, d = i & 127;
        s_wbT[h][d] = dn_wb[d * 4 + h];
    }
    if (tid < 128) s_lam[tid] = dn_lam[tid];
    if (tid < 64) { s_hb1[tid] = hb1[tid]; s_hw2[tid] = hw2[tid]; }
    if (tid < 8) s_bg[tid] = b_gate[n0 + tid];
    if (tid < 4) s_bb[tid] = dn_bb[tid];
    for (int i = tid; i < 8192; i += NTH) {
        int n = i >> 7, d = i & 127;
        s_bank[n][d] = slot_mem[i];
    }
    for (int i = tid; i < 1024; i += NTH) {
        int n = i >> 7, d = i & 127;
        g_slots[0][b][n0 + n][d] = s_bank[n0 + n][d];
    }
    gbar(round);

    for (int t = 0; t < 128; t++) {
        const float* xr = x + (b * 128 + t) * 768;
        // ---- layernorm ----
        float ps = 0.f;
        for (int i = tid; i < 768; i += NTH) { float v = xr[i]; s_xn[i] = v; ps += v; }
        ps = wsum(ps); if (lane == 0) s_red[wid] = ps;
        __syncthreads();
        if (tid == 0) { float s = 0; for (int i = 0; i < 8; i++) s += s_red[i]; s_sc[3] = s * (1.f / 768.f); }
        __syncthreads();
        float mu = s_sc[3], pv = 0.f;
        for (int i = tid; i < 768; i += NTH) { float d2 = s_xn[i] - mu; pv += d2 * d2; }
        pv = wsum(pv); if (lane == 0) s_red[wid] = pv;
        __syncthreads();
        if (tid == 0) { float s = 0; for (int i = 0; i < 8; i++) s += s_red[i]; s_sc[3] = rsqrtf(s * (1.f / 768.f) + 1e-5f); }
        __syncthreads();
        float rstd = s_sc[3];
        for (int i = tid; i < 768; i += NTH) s_xn[i] = (s_xn[i] - mu) * rstd * ln_w[i] + ln_b[i];
        __syncthreads();
        // ---- qk slice (16 entries per block) ----
        {
            int e = sub * 16 + wid * 2;
            #pragma unroll
            for (int sel = 0; sel < 2; sel++) {
                const float* Mr = &g_M[e + sel][0];
                float a = 0.f;
                #pragma unroll
                for (int i = lane; i < 768; i += 32) a += s_xn[i] * Mr[i];
                a = wsum(a);
                if (lane == 0) __stcg(&g_qk[b][e + sel], a);
            }
        }
        float accl = 0.f, reml = 1.f;
        csync();                                   // intra-batch: qk + prior-step slot writes
        if (tid < 128) s_qk[tid] = __ldcg(&g_qk[b][tid]);
        __syncthreads();

        // ================= tick loop =================
        int texec = 8;
        for (int tt = 0; tt < 8; tt++) {
            const unsigned gtag = gt + (unsigned)tt + 1u;   // tag for this tick
            // A: import sibling rows + s_ls
            {
                const float* gsl = &g_slots[p][b][0][0];
                #pragma unroll
                for (int it = 0; it < 8; it++) {
                    int i = it * NTH + tid;
                    int row = i >> 5, c4 = i & 31;
                    if ((row >> 3) != sub)
                        *(float4*)&s_bank[row][c4 * 4] = __ldcg((const float4*)(gsl + row * 128) + c4);
                }
                for (int i = tid; i < 1024; i += NTH) {
                    int n = i >> 7, d = i & 127;
                    s_ls[n][d] = s_lam[d] * s_bank[n0 + n][d];
                }
            }
            __syncthreads();
            // B: scores
            {
                float4 q4 = *(const float4*)&s_qk[lane * 4];
                float sc[8];
                #pragma unroll
                for (int k2 = 0; k2 < 8; k2++) {
                    int n = wid + (k2 << 3);
                    float4 s4 = *(const float4*)&s_bank[n][lane * 4];
                    sc[k2] = q4.x * s4.x + q4.y * s4.y + q4.z * s4.z + q4.w * s4.w;
                }
                #pragma unroll
                for (int k2 = 0; k2 < 8; k2++) {
                    float a = wsum(sc[k2]);
                    if (lane == 0) s_att[wid + (k2 << 3)] = a * INV_SQRT_D;
                }
            }
            __syncthreads();
            // C: softmax in warp 0
            if (wid == 0) {
                float a0 = s_att[lane], a1 = s_att[lane + 32];
                float m = fmaxf(a0, a1);
                #pragma unroll
                for (int o = 16; o; o >>= 1) m = fmaxf(m, __shfl_xor_sync(0xffffffffu, m, o));
                float e0 = expf(a0 - m), e1 = expf(a1 - m);
                float s = wsum(e0 + e1);
                float inv = 1.f / s;
                s_att[lane] = e0 * inv; s_att[lane + 32] = e1 * inv;
            }
            __syncthreads();
            // D: sbar partials
            {
                int d = tid & 127, ph = tid >> 7;
                float a = 0.f;
                #pragma unroll 8
                for (int n2 = 0; n2 < 32; n2++) a += s_att[ph * 32 + n2] * s_bank[ph * 32 + n2][d];
                s_p2[ph][d] = a;
            }
            __syncthreads();
            // E: ro = sbar @ w_v
            {
                int d = tid & 127, ph = tid >> 7;
                float a = 0.f;
                #pragma unroll 8
                for (int e = 0; e < 64; e++) {
                    float se = s_p2[0][ph * 64 + e] + s_p2[1][ph * 64 + e];
                    a += se * s_wv[(ph * 64 + e) * 128 + d];
                }
                s_pc[ph][d] = a;
            }
            __syncthreads();
            if (tid < 128) s_ro[tid] = s_pc[0][tid] + s_pc[1][tid];
            __syncthreads();
            // F: gate + beta + halt partials
            {
                float4 r4 = *(const float4*)&s_ro[lane * 4];
                float4 w4 = *(const float4*)&s_wg[wid][lane * 4];
                float a = r4.x * w4.x + r4.y * w4.y + r4.z * w4.z + r4.w * w4.w;
                a = wsum(a);
                if (lane == 0) s_gate[wid] = 1.f / (1.f + expf(-(a + s_bg[wid])));
            }
            if (wid < 4) {
                float a = s_ro[lane] * s_wbT[wid][lane] + s_ro[lane + 32] * s_wbT[wid][lane + 32]
                        + s_ro[lane + 64] * s_wbT[wid][lane + 64] + s_ro[lane + 96] * s_wbT[wid][lane + 96];
                a = wsum(a);
                if (lane == 0) s_beta[wid] = 2.f / (1.f + expf(-(a + s_bb[wid])));
            }
            {
                int j = tid & 63, p4 = tid >> 6;
                const float* h1p = s_hw1 + p4 * 32 * 64 + j;
                float a0 = 0.f, a1 = 0.f;
                #pragma unroll
                for (int e = 0; e < 32; e += 2) {
                    a0 += s_ro[p4 * 32 + e] * h1p[e * 64];
                    a1 += s_ro[p4 * 32 + e + 1] * h1p[(e + 1) * 64];
                }
                s_hp[p4][j] = a0 + a1;
            }
            __syncthreads();
            // G: halt finish + mailbox publish
            if (tid < 64)
                s_h1[tid] = fmaxf(s_hp[0][tid] + s_hp[1][tid] + s_hp[2][tid] + s_hp[3][tid] + s_hb1[tid], 0.f);
            __syncthreads();
            if (wid == 0) {
                float pv2 = s_h1[lane] * s_hw2[lane] + s_h1[lane + 32] * s_hw2[lane + 32];
                pv2 = wsum(pv2);
                if (lane == 0) {
                    float hl = 1.f / (1.f + expf(-(pv2 + hb2v)));
                    s_sc[1] = hl;
                    if (sub == 0) {
                        unsigned long long mm = ((unsigned long long)gtag << 32)
                                              | (unsigned long long)__float_as_uint(hl);
                        *(volatile unsigned long long*)&g_hmail[b][gtag & 7] = mm;
                    }
                }
            }
            __syncthreads();
            if (tid < 128) accl += reml * s_ro[tid];
            if (tt < 7) reml *= (1.f - s_sc[1]);
            // H: k & v fused float4 GEMVs from L2
            {
                int dq = lane, part = wid;
                float4 ka = make_float4(0, 0, 0, 0), va = ka;
                #pragma unroll
                for (int e = 0; e < 16; e++) {
                    int ee = part * 16 + e;
                    float r = s_ro[ee];
                    float4 wk4 = __ldcg((const float4*)(dn_wk + ee * 128) + dq);
                    float4 wv4 = __ldcg((const float4*)(dn_wv + ee * 128) + dq);
                    ka.x += r * wk4.x; ka.y += r * wk4.y; ka.z += r * wk4.z; ka.w += r * wk4.w;
                    va.x += r * wv4.x; va.y += r * wv4.y; va.z += r * wv4.z; va.w += r * wv4.w;
                }
                *(float4*)&s_kp[part][dq * 4] = ka;
                *(float4*)&s_vp[part][dq * 4] = va;
            }
            __syncthreads();
            if (tid < 128) {
                float kr = 0.f, vr = 0.f;
                #pragma unroll
                for (int pp = 0; pp < 8; pp++) { kr += s_kp[pp][tid]; vr += s_vp[pp][tid]; }
                float sq = wsum(kr * kr);
                s_k[tid] = kr / (sqrtf(sq) + 1e-6f);
                s_bv[tid] = s_beta[tid >> 5] * vr;
            }
            __syncthreads();
            // I: c partials + u + kh
            {
                int j = tid & 127, ph = tid >> 7;
                const float* wop = s_wo + ph * 64 * 128 + j;
                float a = 0.f;
                #pragma unroll 8
                for (int d2 = 0; d2 < 64; d2++) a += s_bv[ph * 64 + d2] * wop[d2 * 128];
                s_pc[ph][j] = a;
            }
            {
                int j = tid & 127, h0 = tid >> 7;
                #pragma unroll
                for (int q2 = 0; q2 < 2; q2++) {
                    int h = h0 + 2 * q2;
                    const float* wop = s_wo + h * 32 * 128 + j;
                    float a = 0.f;
                    #pragma unroll 8
                    for (int dh = 0; dh < 32; dh++) a += s_k[h * 32 + dh] * wop[dh * 128];
                    s_u[h][j] = s_beta[h] * a;
                }
            }
            {
                const float* srow = s_bank[n0 + wid];
                float t0 = s_k[lane] * srow[lane];
                float t1 = s_k[lane + 32] * srow[lane + 32];
                float t2 = s_k[lane + 64] * srow[lane + 64];
                float t3 = s_k[lane + 96] * srow[lane + 96];
                t0 = wsum(t0); t1 = wsum(t1); t2 = wsum(t2); t3 = wsum(t3);
                if (lane == 0) { s_kh[wid][0] = t0; s_kh[wid][1] = t1; s_kh[wid][2] = t2; s_kh[wid][3] = t3; }
            }
            __syncthreads();
            // J: update GEMM + blend + write
            {
                int n = lane >> 2, j0 = wid * 16 + (lane & 3) * 4;
                float4 c0 = *(const float4*)&s_pc[0][j0];
                float4 c1 = *(const float4*)&s_pc[1][j0];
                float4 r = make_float4(c0.x + c1.x, c0.y + c1.y, c0.z + c1.z, c0.w + c1.w);
                #pragma unroll 4
                for (int d2 = 0; d2 < 128; d2++) {
                    float lv = s_ls[n][d2];
                    float4 w4 = *(const float4*)(s_wo + d2 * 128 + j0);
                    r.x += lv * w4.x; r.y += lv * w4.y; r.z += lv * w4.z; r.w += lv * w4.w;
                }
                #pragma unroll
                for (int h = 0; h < 4; h++) {
                    float kv = s_kh[n][h];
                    const float* uu = s_u[h];
                    r.x -= kv * uu[j0]; r.y -= kv * uu[j0 + 1]; r.z -= kv * uu[j0 + 2]; r.w -= kv * uu[j0 + 3];
                }
                float g = s_gate[n];
                float4 sv = *(const float4*)&s_bank[n0 + n][j0];
                float4 nv;
                nv.x = (1.f - g) * sv.x + g * r.x;
                nv.y = (1.f - g) * sv.y + g * r.y;
                nv.z = (1.f - g) * sv.z + g * r.z;
                nv.w = (1.f - g) * sv.w + g * r.w;
                __stcg((float4*)&g_slots[1 - p][b][n0 + n][j0], nv);
                __syncwarp();
                *(float4*)&s_bank[n0 + n][j0] = nv;
            }
            p ^= 1;
            if (tt < 7) {
                csync();                     // intra-batch slot handoff
                if (tt > 0) {
                    // cross-batch break: spin on 8 tagged mailboxes (usually already present)
                    if (wid == 0) {
                        float hv = 0.f;
                        if (lane < 8) {
                            unsigned long long m;
                            do { m = *(volatile unsigned long long*)&g_hmail[lane][gtag & 7]; }
                            while ((unsigned)(m >> 32) != gtag);
                            hv = __uint_as_float((unsigned)m);
                        }
                        hv = wsum(hv);
                        if (lane == 0) s_sc[2] = ((hv * 0.125f) > 0.5f) ? 1.f : 0.f;
                    }
                    __syncthreads();
                    if (s_sc[2] != 0.f) { texec = tt + 1; break; }
                }
            }
        } // ticks
        gt += (unsigned)texec;

        if (tid < 128) s_acc[tid] = accl;
        __syncthreads();
        // out_t = acc @ w_out (transposed rows, float4)
        if (tid < 96) {
            int jg = sub * 96 + tid;
            const float4* wp = (const float4*)&g_woutT[jg][0];
            float a = 0.f;
            #pragma unroll
            for (int i = 0; i < 32; i++) {
                float4 w4 = __ldcg(wp + i);
                float4 ac = *(const float4*)&s_acc[i * 4];
                a += w4.x * ac.x + w4.y * ac.y + w4.z * ac.z + w4.w * ac.w;
            }
            out[(b * 128 + t) * 768 + jg] = a;
        }
    } // steps

    // slots_final
    {
        float* so = out + 8 * 128 * 768;
        for (int i = tid; i < 1024; i += NTH) {
            int n = i >> 7, d = i & 127;
            so[(b * 64 + n0 + n) * 128 + d] = s_bank[n0 + n][d];
        }
    }
}

extern "C" void kernel_launch(void* const* d_in, const int* in_sizes, int n_in,
                              void* d_out, int out_size) {
    const float* x        = (const float*)d_in[0];
    const float* slot_mem = (const float*)d_in[1];
    const float* ln_w     = (const float*)d_in[2];
    const float* ln_b     = (const float*)d_in[3];
    const float* w_in     = (const float*)d_in[4];
    const float* w_q      = (const float*)d_in[5];
    const float* w_k      = (const float*)d_in[6];
    const float* w_v      = (const float*)d_in[7];
    const float* w_gate   = (const float*)d_in[8];
    const float* b_gate   = (const float*)d_in[9];
    const float* hw1      = (const float*)d_in[10];
    const float* hb1      = (const float*)d_in[11];
    const float* hw2      = (const float*)d_in[12];
    const float* hb2      = (const float*)d_in[13];
    const float* w_out    = (const float*)d_in[14];
    const float* dn_wk    = (const float*)d_in[15];
    const float* dn_wv    = (const float*)d_in[16];
    const float* dn_wb    = (const float*)d_in[17];
    const float* dn_bb    = (const float*)d_in[18];
    const float* dn_lam   = (const float*)d_in[19];
    const float* dn_wo    = (const float*)d_in[20];
    float* out = (float*)d_out;

    void* sa = nullptr;
    cudaGetSymbolAddress(&sa, g_sync);
    cudaMemsetAsync(sa, 0, 2 * sizeof(unsigned), 0);
    void* sm = nullptr;
    cudaGetSymbolAddress(&sm, g_hmail);
    cudaMemsetAsync(sm, 0, 8 * 8 * sizeof(unsigned long long), 0);

    cudaFuncSetAttribute(ssb_kernel, cudaFuncAttributeMaxDynamicSharedMemorySize, 196608);
    ssb_kernel<<<NBLK, NTH, 196608>>>(x, slot_mem, ln_w, ln_b, w_in, w_q, w_k, w_v,
                                      w_gate, b_gate, hw1, hb1, hw2, hb2, w_out,
                                      dn_wk, dn_wv, dn_wb, dn_bb, dn_lam, dn_wo, out);
}

// round 17
// speedup vs baseline: 1.3583x; 1.0086x over previous
#include <cuda_runtime.h>
#include <cstdint>
#include <math.h>

#define NBLK 64
#define NTH  256
#define INV_SQRT_D 0.08838834764831845f

__device__ float    g_slots[2][8][64][128];
__device__ float    g_qk[8][128];
__device__ float    g_wqk[128][128];
__device__ float    g_M[128][768];
__device__ float    g_woutT[768][128];
__device__ unsigned long long g_hmail[8][8];  // per-batch halt mailbox ring
__device__ unsigned g_sync[2];                // startup barrier

__device__ __forceinline__ float wsum(float v) {
    #pragma unroll
    for (int o = 16; o; o >>= 1) v += __shfl_xor_sync(0xffffffffu, v, o);
    return v;
}

__device__ __forceinline__ void gbar(unsigned& round) {
    __syncthreads();
    if (threadIdx.x == 0) {
        __threadfence();
        unsigned tk = atomicAdd(&g_sync[0], 1u);
        if (tk == NBLK - 1u) {
            g_sync[0] = 0u;
            __threadfence();
            *(volatile unsigned*)&g_sync[1] = round + 1u;
        } else {
            while (*(volatile unsigned*)&g_sync[1] < round + 1u) {}
            __threadfence();
        }
    }
    round++;
    __syncthreads();
}

__device__ __forceinline__ void csync() {
    asm volatile("barrier.cluster.arrive.aligned;" ::: "memory");
    asm volatile("barrier.cluster.wait.aligned;"   ::: "memory");
}

__global__ void __launch_bounds__(NTH, 1) __cluster_dims__(8, 1, 1)
ssb_kernel(const float* __restrict__ x,      const float* __restrict__ slot_mem,
           const float* __restrict__ ln_w,   const float* __restrict__ ln_b,
           const float* __restrict__ w_in,   const float* __restrict__ w_q,
           const float* __restrict__ w_k,    const float* __restrict__ w_v,
           const float* __restrict__ w_gate, const float* __restrict__ b_gate,
           const float* __restrict__ hw1,    const float* __restrict__ hb1,
           const float* __restrict__ hw2,    const float* __restrict__ hb2,
           const float* __restrict__ w_out,  const float* __restrict__ dn_wk,
           const float* __restrict__ dn_wv,  const float* __restrict__ dn_wb,
           const float* __restrict__ dn_bb,  const float* __restrict__ dn_lam,
           const float* __restrict__ dn_wo,  float* __restrict__ out)
{
    extern __shared__ float dyn[];
    float* s_wo   = dyn;                                  // dn_wo [d][j]  64KB
    float* s_wv   = dyn + 16384;                          // w_v           64KB
    float (*s_bank)[128] = (float(*)[128])(dyn + 32768);  // 64 slot rows  32KB
    float* s_hw1  = dyn + 40960;                          // hw1 [e][j]    32KB

    __shared__ __align__(16) float s_ls[8][132];
    __shared__ __align__(16) float s_xn[768];
    __shared__ __align__(16) float s_qk[128];
    __shared__ __align__(16) float s_k[128], s_bv[128], s_acc[128];
    __shared__ __align__(16) float s_u[4][128];
    __shared__ __align__(16) float s_p2[2][128], s_pc[2][128];
    __shared__ __align__(16) float s_kp[4][128], s_vp[4][128];
    __shared__ __align__(16) float s_wg[8][128];
    __shared__ __align__(16) float s_wbT[4][128];
    __shared__ float s_hp[2][64];
    __shared__ float s_att[64];
    __shared__ float s_lam[128], s_hb1[64], s_hw2[64];
    __shared__ float s_beta[4], s_gate[8], s_kh[8][4], s_bg[8], s_bb[4];
    __shared__ float s_red[9];
    __shared__ float s_sc[4];

    const int tid = threadIdx.x, lane = tid & 31, wid = tid >> 5;
    const int blk = blockIdx.x, b = blk >> 3, sub = blk & 7, n0 = sub * 8;
    unsigned round = 0;
    unsigned gt = 0;
    int p = 0;
    const float hb2v = hb2[0];

    unsigned int bank_u32;
    asm("{ .reg .u64 t; cvta.to.shared.u64 t, %1; cvt.u32.u64 %0, t; }"
        : "=r"(bank_u32) : "l"((void*)s_bank));

    // ---- one-time precompute: wqk, M, woutT ----
    for (int r = 0; r < 2; r++) {
        int d = blk * 2 + r;
        if (tid < 128) s_xn[tid] = w_q[d * 128 + tid];
        __syncthreads();
        for (int e = wid; e < 128; e += 8) {
            const float* wkr = w_k + e * 128;
            float a = s_xn[lane] * wkr[lane] + s_xn[lane + 32] * wkr[lane + 32]
                    + s_xn[lane + 64] * wkr[lane + 64] + s_xn[lane + 96] * wkr[lane + 96];
            a = wsum(a);
            if (lane == 0) g_wqk[d][e] = a;
        }
        __syncthreads();
    }
    for (int i = tid; i < 12 * 128; i += NTH) {
        int r = i >> 7, d = i & 127;
        g_woutT[blk * 12 + r][d] = w_out[d * 768 + blk * 12 + r];
    }
    gbar(round);
    for (int r = 0; r < 2; r++) {
        int e = blk * 2 + r;
        if (tid < 128) s_xn[tid] = __ldcg(&g_wqk[tid][e]);
        __syncthreads();
        for (int i = tid; i < 768; i += NTH) {
            const float* wir = w_in + i * 128;
            float a = 0.f;
            #pragma unroll 8
            for (int d = 0; d < 128; d++) a += wir[d] * s_xn[d];
            g_M[e][i] = a;
        }
        __syncthreads();
    }

    // ---- smem caches ----
    for (int i = tid * 4; i < 16384; i += NTH * 4) {
        *(float4*)(s_wo + i) = *(const float4*)(dn_wo + i);
        *(float4*)(s_wv + i) = *(const float4*)(w_v + i);
    }
    for (int i = tid * 4; i < 8192; i += NTH * 4)
        *(float4*)(s_hw1 + i) = *(const float4*)(hw1 + i);
    for (int i = tid; i < 1024; i += NTH) {
        int n = i >> 7, d = i & 127;
        s_wg[n][d] = w_gate[d * 64 + (n0 + n)];
    }
    for (int i = tid; i < 512; i += NTH) {
        int h = i >> 7, d = i & 127;
        s_wbT[h][d] = dn_wb[d * 4 + h];
    }
    if (tid < 128) s_lam[tid] = dn_lam[tid];
    if (tid < 64) { s_hb1[tid] = hb1[tid]; s_hw2[tid] = hw2[tid]; }
    if (tid < 8) s_bg[tid] = b_gate[n0 + tid];
    if (tid < 4) s_bb[tid] = dn_bb[tid];
    for (int i = tid; i < 8192; i += NTH) {
        int n = i >> 7, d = i & 127;
        s_bank[n][d] = slot_mem[i];
    }
    for (int i = tid; i < 1024; i += NTH) {
        int n = i >> 7, d = i & 127;
        g_slots[0][b][n0 + n][d] = s_bank[n0 + n][d];
    }
    gbar(round);

    for (int t = 0; t < 128; t++) {
        const float* xr = x + (b * 128 + t) * 768;
        // ---- layernorm ----
        float ps = 0.f;
        for (int i = tid; i < 768; i += NTH) { float v = xr[i]; s_xn[i] = v; ps += v; }
        ps = wsum(ps); if (lane == 0) s_red[wid] = ps;
        __syncthreads();
        if (tid == 0) { float s = 0; for (int i = 0; i < 8; i++) s += s_red[i]; s_sc[3] = s * (1.f / 768.f); }
        __syncthreads();
        float mu = s_sc[3], pv = 0.f;
        for (int i = tid; i < 768; i += NTH) { float d2 = s_xn[i] - mu; pv += d2 * d2; }
        pv = wsum(pv); if (lane == 0) s_red[wid] = pv;
        __syncthreads();
        if (tid == 0) { float s = 0; for (int i = 0; i < 8; i++) s += s_red[i]; s_sc[3] = rsqrtf(s * (1.f / 768.f) + 1e-5f); }
        __syncthreads();
        float rstd = s_sc[3];
        for (int i = tid; i < 768; i += NTH) s_xn[i] = (s_xn[i] - mu) * rstd * ln_w[i] + ln_b[i];
        __syncthreads();
        // ---- qk slice (16 entries per block) ----
        {
            int e = sub * 16 + wid * 2;
            #pragma unroll
            for (int sel = 0; sel < 2; sel++) {
                const float* Mr = &g_M[e + sel][0];
                float a = 0.f;
                #pragma unroll
                for (int i = lane; i < 768; i += 32) a += s_xn[i] * Mr[i];
                a = wsum(a);
                if (lane == 0) __stcg(&g_qk[b][e + sel], a);
            }
        }
        float accl = 0.f, reml = 1.f;
        csync();                                   // qk + prior-step slot writes
        if (tid < 128) s_qk[tid] = __ldcg(&g_qk[b][tid]);
        if (t < 127 && tid < 24)                   // warm L2 for next step's x row
            asm volatile("prefetch.global.L2 [%0];" :: "l"(x + (b * 128 + t + 1) * 768 + tid * 32));
        __syncthreads();

        // ================= tick loop =================
        int texec = 8;
        for (int tt = 0; tt < 8; tt++) {
            const unsigned gtag = gt + (unsigned)tt + 1u;
            // A: cp.async import of sibling rows, overlapped with s_ls
            {
                const float* gsl = &g_slots[p][b][0][0];
                #pragma unroll
                for (int it = 0; it < 8; it++) {
                    int i = it * NTH + tid;
                    int row = i >> 5, c4 = i & 31;
                    if ((row >> 3) != sub) {
                        unsigned int dst = bank_u32 + (unsigned int)(row * 128 + c4 * 4) * 4u;
                        asm volatile("cp.async.cg.shared.global [%0], [%1], 16;"
                                     :: "r"(dst), "l"(gsl + row * 128 + c4 * 4) : "memory");
                    }
                }
                for (int i = tid; i < 1024; i += NTH) {
                    int n = i >> 7, d = i & 127;
                    s_ls[n][d] = s_lam[d] * s_bank[n0 + n][d];
                }
                asm volatile("cp.async.wait_all;" ::: "memory");
            }
            __syncthreads();
            // B: scores
            {
                float4 q4 = *(const float4*)&s_qk[lane * 4];
                float sc[8];
                #pragma unroll
                for (int k2 = 0; k2 < 8; k2++) {
                    int n = wid + (k2 << 3);
                    float4 s4 = *(const float4*)&s_bank[n][lane * 4];
                    sc[k2] = q4.x * s4.x + q4.y * s4.y + q4.z * s4.z + q4.w * s4.w;
                }
                #pragma unroll
                for (int k2 = 0; k2 < 8; k2++) {
                    float a = wsum(sc[k2]);
                    if (lane == 0) s_att[wid + (k2 << 3)] = a * INV_SQRT_D;
                }
            }
            __syncthreads();
            // C: softmax in warp 0
            if (wid == 0) {
                float a0 = s_att[lane], a1 = s_att[lane + 32];
                float m = fmaxf(a0, a1);
                #pragma unroll
                for (int o = 16; o; o >>= 1) m = fmaxf(m, __shfl_xor_sync(0xffffffffu, m, o));
                float e0 = expf(a0 - m), e1 = expf(a1 - m);
                float s = wsum(e0 + e1);
                float inv = 1.f / s;
                s_att[lane] = e0 * inv; s_att[lane + 32] = e1 * inv;
            }
            __syncthreads();
            // D: sbar partials -> s_p2
            {
                int d = tid & 127, ph = tid >> 7;
                float a = 0.f;
                #pragma unroll 8
                for (int n2 = 0; n2 < 32; n2++) a += s_att[ph * 32 + n2] * s_bank[ph * 32 + n2][d];
                s_p2[ph][d] = a;
            }
            __syncthreads();
            // E: ro partials -> s_pc (no combine stage)
            {
                int d = tid & 127, ph = tid >> 7;
                float a = 0.f;
                #pragma unroll 8
                for (int e = 0; e < 64; e++) {
                    float se = s_p2[0][ph * 64 + e] + s_p2[1][ph * 64 + e];
                    a += se * s_wv[(ph * 64 + e) * 128 + d];
                }
                s_pc[ph][d] = a;
            }
            __syncthreads();
            // F (warps 0-3): gate+beta+halt  ||  H (warps 4-7): k/v GEMV
            if (tid < 128) {
                #pragma unroll
                for (int s2 = 0; s2 < 2; s2++) {
                    int n = wid * 2 + s2;
                    float4 p0 = *(const float4*)&s_pc[0][lane * 4];
                    float4 p1 = *(const float4*)&s_pc[1][lane * 4];
                    float4 w4 = *(const float4*)&s_wg[n][lane * 4];
                    float a = (p0.x + p1.x) * w4.x + (p0.y + p1.y) * w4.y
                            + (p0.z + p1.z) * w4.z + (p0.w + p1.w) * w4.w;
                    a = wsum(a);
                    if (lane == 0) s_gate[n] = 1.f / (1.f + expf(-(a + s_bg[n])));
                }
                {
                    float a = 0.f;
                    #pragma unroll
                    for (int q2 = 0; q2 < 4; q2++) {
                        int i = lane + q2 * 32;
                        a += (s_pc[0][i] + s_pc[1][i]) * s_wbT[wid][i];
                    }
                    a = wsum(a);
                    if (lane == 0) s_beta[wid] = 2.f / (1.f + expf(-(a + s_bb[wid])));
                }
                {
                    int j = tid & 63, half = tid >> 6;
                    const float* h1p = s_hw1 + half * 64 * 64 + j;
                    float a0 = 0.f, a1 = 0.f;
                    #pragma unroll
                    for (int e = 0; e < 64; e += 2) {
                        int e0i = half * 64 + e;
                        a0 += (s_pc[0][e0i] + s_pc[1][e0i]) * h1p[e * 64];
                        a1 += (s_pc[0][e0i + 1] + s_pc[1][e0i + 1]) * h1p[(e + 1) * 64];
                    }
                    s_hp[half][j] = a0 + a1;
                }
                asm volatile("bar.sync 1, 128;" ::: "memory");
                if (wid == 0) {
                    float h0 = fmaxf(s_hp[0][lane] + s_hp[1][lane] + s_hb1[lane], 0.f);
                    float h1v = fmaxf(s_hp[0][lane + 32] + s_hp[1][lane + 32] + s_hb1[lane + 32], 0.f);
                    float pv2 = h0 * s_hw2[lane] + h1v * s_hw2[lane + 32];
                    pv2 = wsum(pv2);
                    if (lane == 0) {
                        float hl = 1.f / (1.f + expf(-(pv2 + hb2v)));
                        s_sc[1] = hl;
                        if (sub == 0) {
                            unsigned long long mm = ((unsigned long long)gtag << 32)
                                                  | (unsigned long long)__float_as_uint(hl);
                            *(volatile unsigned long long*)&g_hmail[b][gtag & 7] = mm;
                        }
                    }
                }
            } else {
                int part = wid - 4, dq = lane;
                float4 ka = make_float4(0, 0, 0, 0), va = ka;
                #pragma unroll
                for (int e = 0; e < 32; e++) {
                    int ee = part * 32 + e;
                    float r = s_pc[0][ee] + s_pc[1][ee];
                    float4 wk4 = __ldcg((const float4*)(dn_wk + ee * 128) + dq);
                    float4 wv4 = __ldcg((const float4*)(dn_wv + ee * 128) + dq);
                    ka.x += r * wk4.x; ka.y += r * wk4.y; ka.z += r * wk4.z; ka.w += r * wk4.w;
                    va.x += r * wv4.x; va.y += r * wv4.y; va.z += r * wv4.z; va.w += r * wv4.w;
                }
                *(float4*)&s_kp[part][dq * 4] = ka;
                *(float4*)&s_vp[part][dq * 4] = va;
            }
            __syncthreads();
            // acc + reml + k/v combine
            {
                float hl = s_sc[1];
                if (tid < 128) {
                    float ro = s_pc[0][tid] + s_pc[1][tid];
                    accl += reml * ro;
                    float kr = s_kp[0][tid] + s_kp[1][tid] + s_kp[2][tid] + s_kp[3][tid];
                    float vr = s_vp[0][tid] + s_vp[1][tid] + s_vp[2][tid] + s_vp[3][tid];
                    float sq = wsum(kr * kr);
                    s_k[tid] = kr / (sqrtf(sq) + 1e-6f);
                    s_bv[tid] = s_beta[tid >> 5] * vr;
                }
                if (tt < 7) reml *= (1.f - hl);
            }
            __syncthreads();
            // I: c partials -> s_p2, u, kh
            {
                int j = tid & 127, ph = tid >> 7;
                const float* wop = s_wo + ph * 64 * 128 + j;
                float a = 0.f;
                #pragma unroll 8
                for (int d2 = 0; d2 < 64; d2++) a += s_bv[ph * 64 + d2] * wop[d2 * 128];
                s_p2[ph][j] = a;
            }
            {
                int j = tid & 127, h0 = tid >> 7;
                #pragma unroll
                for (int q2 = 0; q2 < 2; q2++) {
                    int h = h0 + 2 * q2;
                    const float* wop = s_wo + h * 32 * 128 + j;
                    float a = 0.f;
                    #pragma unroll 8
                    for (int dh = 0; dh < 32; dh++) a += s_k[h * 32 + dh] * wop[dh * 128];
                    s_u[h][j] = s_beta[h] * a;
                }
            }
            {
                const float* srow = s_bank[n0 + wid];
                float t0 = s_k[lane] * srow[lane];
                float t1 = s_k[lane + 32] * srow[lane + 32];
                float t2 = s_k[lane + 64] * srow[lane + 64];
                float t3 = s_k[lane + 96] * srow[lane + 96];
                t0 = wsum(t0); t1 = wsum(t1); t2 = wsum(t2); t3 = wsum(t3);
                if (lane == 0) { s_kh[wid][0] = t0; s_kh[wid][1] = t1; s_kh[wid][2] = t2; s_kh[wid][3] = t3; }
            }
            __syncthreads();
            // J: update GEMM (packed f32x2) + blend + write
            {
                int n = lane >> 2, j0 = wid * 16 + (lane & 3) * 4;
                float cx = s_p2[0][j0]     + s_p2[1][j0];
                float cy = s_p2[0][j0 + 1] + s_p2[1][j0 + 1];
                float cz = s_p2[0][j0 + 2] + s_p2[1][j0 + 2];
                float cw = s_p2[0][j0 + 3] + s_p2[1][j0 + 3];
                unsigned long long r01, r23;
                asm("mov.b64 %0, {%1, %2};" : "=l"(r01) : "f"(cx), "f"(cy));
                asm("mov.b64 %0, {%1, %2};" : "=l"(r23) : "f"(cz), "f"(cw));
                #pragma unroll 4
                for (int d2 = 0; d2 < 128; d2++) {
                    float lv = s_ls[n][d2];
                    unsigned long long lv2;
                    asm("mov.b64 %0, {%1, %1};" : "=l"(lv2) : "f"(lv));
                    ulonglong2 w2 = *(const ulonglong2*)(s_wo + d2 * 128 + j0);
                    asm("fma.rn.f32x2 %0, %1, %2, %0;" : "+l"(r01) : "l"(w2.x), "l"(lv2));
                    asm("fma.rn.f32x2 %0, %1, %2, %0;" : "+l"(r23) : "l"(w2.y), "l"(lv2));
                }
                float rx, ry, rz, rw;
                asm("mov.b64 {%0, %1}, %2;" : "=f"(rx), "=f"(ry) : "l"(r01));
                asm("mov.b64 {%0, %1}, %2;" : "=f"(rz), "=f"(rw) : "l"(r23));
                #pragma unroll
                for (int h = 0; h < 4; h++) {
                    float kv = s_kh[n][h];
                    const float* uu = s_u[h];
                    rx -= kv * uu[j0]; ry -= kv * uu[j0 + 1]; rz -= kv * uu[j0 + 2]; rw -= kv * uu[j0 + 3];
                }
                float g = s_gate[n];
                float4 sv = *(const float4*)&s_bank[n0 + n][j0];
                float4 nv;
                nv.x = (1.f - g) * sv.x + g * rx;
                nv.y = (1.f - g) * sv.y + g * ry;
                nv.z = (1.f - g) * sv.z + g * rz;
                nv.w = (1.f - g) * sv.w + g * rw;
                __stcg((float4*)&g_slots[1 - p][b][n0 + n][j0], nv);
                __syncwarp();
                *(float4*)&s_bank[n0 + n][j0] = nv;
            }
            p ^= 1;
            if (tt < 7) {
                csync();
                if (tt > 0) {
                    if (wid == 0) {
                        float hv = 0.f;
                        if (lane < 8) {
                            unsigned long long m;
                            do { m = *(volatile unsigned long long*)&g_hmail[lane][gtag & 7]; }
                            while ((unsigned)(m >> 32) != gtag);
                            hv = __uint_as_float((unsigned)m);
                        }
                        hv = wsum(hv);
                        if (lane == 0) s_sc[2] = ((hv * 0.125f) > 0.5f) ? 1.f : 0.f;
                    }
                    __syncthreads();
                    if (s_sc[2] != 0.f) { texec = tt + 1; break; }
                }
            }
        } // ticks
        gt += (unsigned)texec;

        if (tid < 128) s_acc[tid] = accl;
        __syncthreads();
        if (tid < 96) {
            int jg = sub * 96 + tid;
            const float4* wp = (const float4*)&g_woutT[jg][0];
            float a = 0.f;
            #pragma unroll
            for (int i = 0; i < 32; i++) {
                float4 w4 = __ldcg(wp + i);
                float4 ac = *(const float4*)&s_acc[i * 4];
                a += w4.x * ac.x + w4.y * ac.y + w4.z * ac.z + w4.w * ac.w;
            }
            out[(b * 128 + t) * 768 + jg] = a;
        }
    } // steps

    // slots_final
    {
        float* so = out + 8 * 128 * 768;
        for (int i = tid; i < 1024; i += NTH) {
            int n = i >> 7, d = i & 127;
            so[(b * 64 + n0 + n) * 128 + d] = s_bank[n0 + n][d];
        }
    }
}

extern "C" void kernel_launch(void* const* d_in, const int* in_sizes, int n_in,
                              void* d_out, int out_size) {
    const float* x        = (const float*)d_in[0];
    const float* slot_mem = (const float*)d_in[1];
    const float* ln_w     = (const float*)d_in[2];
    const float* ln_b     = (const float*)d_in[3];
    const float* w_in     = (const float*)d_in[4];
    const float* w_q      = (const float*)d_in[5];
    const float* w_k      = (const float*)d_in[6];
    const float* w_v      = (const float*)d_in[7];
    const float* w_gate   = (const float*)d_in[8];
    const float* b_gate   = (const float*)d_in[9];
    const float* hw1      = (const float*)d_in[10];
    const float* hb1      = (const float*)d_in[11];
    const float* hw2      = (const float*)d_in[12];
    const float* hb2      = (const float*)d_in[13];
    const float* w_out    = (const float*)d_in[14];
    const float* dn_wk    = (const float*)d_in[15];
    const float* dn_wv    = (const float*)d_in[16];
    const float* dn_wb    = (const float*)d_in[17];
    const float* dn_bb    = (const float*)d_in[18];
    const float* dn_lam   = (const float*)d_in[19];
    const float* dn_wo    = (const float*)d_in[20];
    float* out = (float*)d_out;

    void* sa = nullptr;
    cudaGetSymbolAddress(&sa, g_sync);
    cudaMemsetAsync(sa, 0, 2 * sizeof(unsigned), 0);
    void* sm = nullptr;
    cudaGetSymbolAddress(&sm, g_hmail);
    cudaMemsetAsync(sm, 0, 8 * 8 * sizeof(unsigned long long), 0);

    cudaFuncSetAttribute(ssb_kernel, cudaFuncAttributeMaxDynamicSharedMemorySize, 196608);
    ssb_kernel<<<NBLK, NTH, 196608>>>(x, slot_mem, ln_w, ln_b, w_in, w_q, w_k, w_v,
                                      w_gate, b_gate, hw1, hb1, hw2, hb2, w_out,
                                      dn_wk, dn_wv, dn_wb, dn_bb, dn_lam, dn_wo, out);
}